// round 6
// baseline (speedup 1.0000x reference)
#include <cuda_runtime.h>
#include <math.h>

#define EPSF 1e-6f
#define HANDS 32
#define BLKT 160   // 32 hands x 5 finger-warps

struct V3 { float x, y, z; };

__device__ __forceinline__ V3 operator+(V3 a, V3 b){ return {a.x+b.x, a.y+b.y, a.z+b.z}; }
__device__ __forceinline__ V3 operator-(V3 a, V3 b){ return {a.x-b.x, a.y-b.y, a.z-b.z}; }
__device__ __forceinline__ V3 operator*(V3 a, float s){ return {a.x*s, a.y*s, a.z*s}; }
__device__ __forceinline__ float dot3(V3 a, V3 b){ return a.x*b.x + a.y*b.y + a.z*b.z; }
__device__ __forceinline__ V3 cross3(V3 a, V3 b){
    return { a.y*b.z - a.z*b.y, a.z*b.x - a.x*b.z, a.x*b.y - a.y*b.x };
}
__device__ __forceinline__ float nrm3(V3 a){ return sqrtf(dot3(a,a)); }
__device__ __forceinline__ V3 unitv(V3 a){
    float inv = __fdividef(1.0f, nrm3(a)+EPSF); return a*inv;
}
__device__ __forceinline__ float clampd(float x){ return fminf(fmaxf(x, -1.0f+EPSF), 1.0f-EPSF); }

struct M3 { float a[9]; };

__device__ __forceinline__ V3 mv(const M3& R, V3 v){
    return { R.a[0]*v.x + R.a[1]*v.y + R.a[2]*v.z,
             R.a[3]*v.x + R.a[4]*v.y + R.a[5]*v.z,
             R.a[6]*v.x + R.a[7]*v.y + R.a[8]*v.z };
}

// smem joint accessors; with compile-time j these become LDS/STS with immediate offsets
template<int J>
__device__ __forceinline__ V3 ld3(const float* sp){
    return { sp[3*J], sp[3*J+1], sp[3*J+2] };
}
template<int J>
__device__ __forceinline__ void st3(float* sp, V3 v){
    sp[3*J] = v.x; sp[3*J+1] = v.y; sp[3*J+2] = v.z;
}

// Rodrigues matrix from UNIT axis
__device__ __forceinline__ M3 rotmat_u(V3 a, float c, float s){
    float C = 1.0f - c;
    M3 R;
    R.a[0] = c + a.x*a.x*C;     R.a[1] = a.x*a.y*C - a.z*s; R.a[2] = a.x*a.z*C + a.y*s;
    R.a[3] = a.y*a.x*C + a.z*s; R.a[4] = c + a.y*a.y*C;     R.a[5] = a.y*a.z*C - a.x*s;
    R.a[6] = a.z*a.x*C - a.y*s; R.a[7] = a.z*a.y*C + a.x*s; R.a[8] = c + a.z*a.z*C;
    return R;
}

// Sign-resolved rotation: d0=(R(+)sv)·ev = t1+t2 ; d1=(R(-)sv)·ev = t1-t2.
// |d0|>|d1| <=> t1*t2>0 ; reference picks R(-) on tie.
__device__ __forceinline__ M3 pick_rot(V3 a, float c, float s, V3 sv, V3 ev){
    float C  = 1.0f - c;
    float t1 = c*dot3(sv, ev) + C*dot3(a, sv)*dot3(a, ev);
    float t2 = s*dot3(cross3(a, sv), ev);
    if (!(t1*t2 > 0.0f)) s = -s;
    return rotmat_u(a, c, s);
}

// getrot for abduction (angle scaled by flexRatio -> real sincos)
__device__ __forceinline__ M3 getrot(float angle, float flexRatio, V3 axisU, V3 sv, V3 ev){
    const float ANGLEP = 0.34906585039886590f;  // pi/9
    const float TH120  = 2.09439506666666650f;  // 3.1415926/180*120
    angle = (angle > TH120) ? (3.1415926f - angle) : angle;
    float dif = fmaxf(angle - ANGLEP, 0.0f) * flexRatio;
    float s, c;
    sincosf(dif, &s, &c);
    return pick_rot(axisU, c, s, sv, ev);
}

// Smallest eigenvector of symmetric 3x3 (analytic + one Rayleigh refinement).
__device__ __forceinline__ V3 smallest_evec(float a00, float a01, float a02,
                                            float a11, float a12, float a22){
    float m   = (a00 + a11 + a22) * (1.0f/3.0f);
    float b00 = a00 - m, b11 = a11 - m, b22 = a22 - m;
    float p1  = a01*a01 + a02*a02 + a12*a12;
    float p2  = b00*b00 + b11*b11 + b22*b22 + 2.0f*p1;
    float p   = sqrtf(fmaxf(p2*(1.0f/6.0f), 1e-30f));
    float invp = __fdividef(1.0f, p);
    float det = b00*(b11*b22 - a12*a12)
              - a01*(a01*b22 - a12*a02)
              + a02*(a01*a12 - b11*a02);
    float r = det * 0.5f * invp*invp*invp;
    r = fminf(fmaxf(r, -1.0f), 1.0f);
    float phi = acosf(r) * (1.0f/3.0f);
    float lam = m + 2.0f*p*cosf(phi + 2.0943951023931953f); // smallest eigenvalue

    V3 v;
    #pragma unroll
    for (int it = 0; it < 2; it++) {
        V3 r0 = { a00 - lam, a01, a02 };
        V3 r1 = { a01, a11 - lam, a12 };
        V3 r2 = { a02, a12, a22 - lam };
        V3 c0 = cross3(r0, r1), c1 = cross3(r0, r2), c2 = cross3(r1, r2);
        float l0 = dot3(c0,c0), l1 = dot3(c1,c1), l2 = dot3(c2,c2);
        V3 best = c0; float lb = l0;
        if (l1 > lb) { best = c1; lb = l1; }
        if (l2 > lb) { best = c2; lb = l2; }
        v = best * rsqrtf(fmaxf(lb, 1e-30f));
        if (it < 1) {
            float Av0 = a00*v.x + a01*v.y + a02*v.z;
            float Av1 = a01*v.x + a11*v.y + a12*v.z;
            float Av2 = a02*v.x + a12*v.y + a22*v.z;
            lam = v.x*Av0 + v.y*Av1 + v.z*Av2;
        }
    }
    return v;
}

// planarize one finger (4 joints in smem, modified in place)
template<int I0, int I1, int I2, int I3>
__device__ __forceinline__ void plan4(float* sp){
    V3 p0 = ld3<I0>(sp), p1 = ld3<I1>(sp), p2 = ld3<I2>(sp), p3 = ld3<I3>(sp);
    V3 cm = (p0 + p1 + p2 + p3) * 0.25f;
    V3 d0 = p0 - cm, d1 = p1 - cm, d2 = p2 - cm, d3 = p3 - cm;
    float a00 = d0.x*d0.x + d1.x*d1.x + d2.x*d2.x + d3.x*d3.x;
    float a01 = d0.x*d0.y + d1.x*d1.y + d2.x*d2.y + d3.x*d3.y;
    float a02 = d0.x*d0.z + d1.x*d1.z + d2.x*d2.z + d3.x*d3.z;
    float a11 = d0.y*d0.y + d1.y*d1.y + d2.y*d2.y + d3.y*d3.y;
    float a12 = d0.y*d0.z + d1.y*d1.z + d2.y*d2.z + d3.y*d3.z;
    float a22 = d0.z*d0.z + d1.z*d1.z + d2.z*d2.z + d3.z*d3.z;
    V3 n = smallest_evec(a00, a01, a02, a11, a12, a22);
    float vd = -dot3(n, cm);
    float t;
    t = dot3(p0, n) + vd; st3<I0>(sp, p0 - n*t);
    t = dot3(p1, n) + vd; st3<I1>(sp, p1 - n*t);
    t = dot3(p2, n) + vd; st3<I2>(sp, p2 - n*t);
    t = dot3(p3, n) + vd; st3<I3>(sp, p3 - n*t);
}

// abduction for one finger; RECTC/RECTS compile-time (thumb: 1,0 -> rect folds away)
template<int IB, int IMCP, int IPIP, int IDIP, int ITIP>
__device__ __forceinline__ void abduct(float* sp, float RECTC, float RECTS){
    V3 w  = ld3<0>(sp);
    V3 mcp = ld3<IMCP>(sp), pip = ld3<IPIP>(sp);
    V3 pa = mcp - w, pb = ld3<IB>(sp) - w;

    V3 palm = unitv(cross3(pa, pb));
    float vd   = -dot3(mcp, palm);
    float dist = dot3(pip, palm) + vd;
    V3 projpip = pip - palm*dist;

    V3 d  = pip - mcp;
    float dis = nrm3(d);
    float invdis = __fdividef(1.0f, dis + EPSF);
    V3 mcppip = d * invdis;

    V3 e  = projpip - mcp;
    float lene = nrm3(e);
    V3 mcpproj = e * __fdividef(1.0f, lene + EPSF);
    float flex = lene * invdis;
    flex = (flex < 0.3f) ? 0.0f : flex;

    V3 wristmcp = unitv(mcp - w);
    float cv = clampd(dot3(wristmcp, mcppip));
    bool overflex = cv < 0.00079632671073326f;   // == acos(cv) > 1.57

    // rect = R(palm, RECTIFY) * wristmcp  via vector Rodrigues (palm ~ unit)
    float Cr = 1.0f - RECTC;
    V3 axw = cross3(palm, wristmcp);
    float adw = dot3(palm, wristmcp);
    V3 rect = wristmcp*RECTC + axw*RECTS + palm*(adw*Cr);

    float ang = acosf(clampd(dot3(rect, mcpproj)));
    if (overflex) ang = 0.0f;
    M3 R = getrot(ang, flex, palm, mcpproj, wristmcp);

    st3<IPIP>(sp, mv(R, pip - mcp) + mcp);
    V3 c;
    c = ld3<IDIP>(sp); st3<IDIP>(sp, mv(R, c - mcp) + mcp);
    c = ld3<ITIP>(sp); st3<ITIP>(sp, mv(R, c - mcp) + mcp);
}

// plane rotation (flexRatio==1 -> analytic cos/sin of (a - pi/9), no acos/sincos)
template<int IB, int IMCP, int IPIP, int IDIP, int ITIP>
__device__ __forceinline__ void planerot(float* sp){
    const float COS_TH120 = -0.49999997f;      // cos(3.1415926/180*120)
    const float cAP = 0.93969262078590838f;    // cos(pi/9)
    const float sAP = 0.34202014332566871f;    // sin(pi/9)

    V3 w  = ld3<0>(sp);
    V3 mcp = ld3<IMCP>(sp), pip = ld3<IPIP>(sp), dip = ld3<IDIP>(sp);
    V3 pa = mcp - w, pb = ld3<IB>(sp) - w;

    V3 mcppip = unitv(pip - mcp);
    V3 pipdip = unitv(dip - pip);
    bool maskline = fabsf(dot3(mcppip, pipdip)) > 0.95f;
    V3 cdir = unitv(cross3(mcppip, pipdip));
    V3 palm = unitv(cross3(pa, pb));
    V3 stdv = unitv(cross3(unitv(mcp - w), palm));

    float x = clampd(dot3(cdir, stdv));
    float ca = (x < COS_TH120) ? -x : x;
    float sa = sqrtf(fmaxf(1.0f - x*x, 0.0f));
    if (maskline) { ca = 1.0f; sa = 0.0f; }

    float c, s;
    if (ca >= cAP) { c = 1.0f; s = 0.0f; }
    else { c = ca*cAP + sa*sAP; s = sa*cAP - ca*sAP; }
    M3 R = pick_rot(mcppip, c, s, cdir, stdv);

    st3<IDIP>(sp, mv(R, dip - pip) + pip);
    V3 cc = ld3<ITIP>(sp);
    st3<ITIP>(sp, mv(R, cc - pip) + pip);
}

// full per-finger pipeline after the first planarize barrier (warp-uniform call)
template<int IB, int IMCP, int IPIP, int IDIP, int ITIP, bool DO_PR>
__device__ __forceinline__ void finger_rest(float* sp, float RECTC, float RECTS){
    abduct<IB, IMCP, IPIP, IDIP, ITIP>(sp, RECTC, RECTS);
    if (DO_PR) planerot<IB, IMCP, IPIP, IDIP, ITIP>(sp);
    plan4<IMCP, IPIP, IDIP, ITIP>(sp);
}

__global__ void __launch_bounds__(BLKT, 6)
handpose_kernel(const float* __restrict__ in, float* __restrict__ out, int N){
    __shared__ float s[HANDS * 63];
    int base = blockIdx.x * HANDS;
    int nE = N - base; if (nE > HANDS) nE = HANDS;
    int nF = nE * 63;
    const float* gin = in + (long long)base * 63;

    if (nE == HANDS) {
        const float4* g4 = (const float4*)gin;   // base*63*4 B divisible by 16
        float4* s4 = (float4*)s;
        for (int k = threadIdx.x; k < (HANDS*63)/4; k += BLKT)
            s4[k] = g4[k];
    } else {
        for (int k = threadIdx.x; k < nF; k += BLKT) s[k] = gin[k];
    }
    __syncthreads();

    int lane = threadIdx.x & 31;   // hand within block
    int f    = threadIdx.x >> 5;   // finger (uniform per warp)
    bool act = lane < nE;
    float* sp = s + lane * 63;

    // ---- planarize #1 (warp-uniform switch, immediate smem offsets) ----
    if (act) {
        switch (f) {
            case 0: plan4<1, 2, 3, 17>(sp); break;
            case 1: plan4<4, 5, 6, 18>(sp); break;
            case 2: plan4<10, 11, 12, 19>(sp); break;
            case 3: plan4<7, 8, 9, 20>(sp); break;
            default: plan4<13, 14, 15, 16>(sp); break;
        }
    }
    __syncthreads();   // abduction reads neighbor MCPs written above

    if (act) {
        switch (f) {
            case 0: finger_rest<4, 1, 2, 3, 17, true >(sp, 0.98219268f,  0.18787768f); break;
            case 1: finger_rest<10, 4, 5, 6, 18, true >(sp, 0.99115533f,  0.13270742f); break;
            case 2: finger_rest<7, 10, 11, 12, 19, true >(sp, 0.98890531f, -0.14855814f); break;
            case 3: finger_rest<1, 7, 8, 9, 20, true >(sp, 0.99939799f,  0.03469304f); break;
            default: finger_rest<1, 13, 14, 15, 16, false>(sp, 1.0f, 0.0f); break;
        }
    }
    __syncthreads();

    float* gout = out + (long long)base * 63;
    if (nE == HANDS) {
        const float4* s4 = (const float4*)s;
        float4* g4 = (float4*)gout;
        for (int k = threadIdx.x; k < (HANDS*63)/4; k += BLKT)
            g4[k] = s4[k];
    } else {
        for (int k = threadIdx.x; k < nF; k += BLKT) gout[k] = s[k];
    }
}

extern "C" void kernel_launch(void* const* d_in, const int* in_sizes, int n_in,
                              void* d_out, int out_size){
    const float* in = (const float*)d_in[0];
    float* out = (float*)d_out;
    int N = in_sizes[0] / 63;
    int grid = (N + HANDS - 1) / HANDS;
    handpose_kernel<<<grid, BLKT>>>(in, out, N);
}

// round 7
// speedup vs baseline: 1.6318x; 1.6318x over previous
#include <cuda_runtime.h>
#include <math.h>

#define EPSF 1e-6f
#define HANDS 32
#define BLKT 160   // 32 hands x 5 finger-warps

struct V3 { float x, y, z; };

__device__ __forceinline__ V3 operator+(V3 a, V3 b){ return {a.x+b.x, a.y+b.y, a.z+b.z}; }
__device__ __forceinline__ V3 operator-(V3 a, V3 b){ return {a.x-b.x, a.y-b.y, a.z-b.z}; }
__device__ __forceinline__ V3 operator*(V3 a, float s){ return {a.x*s, a.y*s, a.z*s}; }
__device__ __forceinline__ float dot3(V3 a, V3 b){ return a.x*b.x + a.y*b.y + a.z*b.z; }
__device__ __forceinline__ V3 cross3(V3 a, V3 b){
    return { a.y*b.z - a.z*b.y, a.z*b.x - a.x*b.z, a.x*b.y - a.y*b.x };
}
__device__ __forceinline__ float nrm3(V3 a){ return sqrtf(dot3(a,a)); }
__device__ __forceinline__ V3 unitv(V3 a){
    float inv = __fdividef(1.0f, nrm3(a)+EPSF); return a*inv;
}
__device__ __forceinline__ float clampd(float x){ return fminf(fmaxf(x, -1.0f+EPSF), 1.0f-EPSF); }

struct M3 { float a[9]; };

__device__ __forceinline__ V3 mv(const M3& R, V3 v){
    return { R.a[0]*v.x + R.a[1]*v.y + R.a[2]*v.z,
             R.a[3]*v.x + R.a[4]*v.y + R.a[5]*v.z,
             R.a[6]*v.x + R.a[7]*v.y + R.a[8]*v.z };
}

// pointer-based joint accessors: LDS/STS with immediate offsets off one register
__device__ __forceinline__ V3 ld3p(const float* p){ return { p[0], p[1], p[2] }; }
__device__ __forceinline__ void st3p(float* p, V3 v){ p[0] = v.x; p[1] = v.y; p[2] = v.z; }

// per-finger tables
__constant__ int   cMCP[5] = {1, 4, 10, 7, 13};
__constant__ int   cPB [5] = {4, 10, 7, 1, 1};           // palm b index (a index == MCP)
__constant__ float cRC [5] = {0.98219268f, 0.99115533f, 0.98890531f, 0.99939799f, 1.0f};
__constant__ float cRS [5] = {0.18787768f, 0.13270742f, -0.14855814f, 0.03469304f, 0.0f};
// PIP/DIP/TIP layouts: fingers 0-3 are MCP,MCP+1,MCP+2 with TIP 17..20; thumb 13,14,15,16

// Rodrigues matrix from UNIT axis
__device__ __forceinline__ M3 rotmat_u(V3 a, float c, float s){
    float C = 1.0f - c;
    M3 R;
    R.a[0] = c + a.x*a.x*C;     R.a[1] = a.x*a.y*C - a.z*s; R.a[2] = a.x*a.z*C + a.y*s;
    R.a[3] = a.y*a.x*C + a.z*s; R.a[4] = c + a.y*a.y*C;     R.a[5] = a.y*a.z*C - a.x*s;
    R.a[6] = a.z*a.x*C - a.y*s; R.a[7] = a.z*a.y*C + a.x*s; R.a[8] = c + a.z*a.z*C;
    return R;
}

// Sign-resolved rotation: d0=(R(+)sv)·ev = t1+t2 ; d1=(R(-)sv)·ev = t1-t2.
// |d0|>|d1| <=> t1*t2>0 ; reference picks R(-) on tie.
__device__ __forceinline__ M3 pick_rot(V3 a, float c, float s, V3 sv, V3 ev){
    float C  = 1.0f - c;
    float t1 = c*dot3(sv, ev) + C*dot3(a, sv)*dot3(a, ev);
    float t2 = s*dot3(cross3(a, sv), ev);
    if (!(t1*t2 > 0.0f)) s = -s;
    return rotmat_u(a, c, s);
}

// getrot for abduction (angle scaled by flexRatio -> real sincos)
__device__ __forceinline__ M3 getrot(float angle, float flexRatio, V3 axisU, V3 sv, V3 ev){
    const float ANGLEP = 0.34906585039886590f;  // pi/9
    const float TH120  = 2.09439506666666650f;  // 3.1415926/180*120
    angle = (angle > TH120) ? (3.1415926f - angle) : angle;
    float dif = fmaxf(angle - ANGLEP, 0.0f) * flexRatio;
    float s, c;
    sincosf(dif, &s, &c);
    return pick_rot(axisU, c, s, sv, ev);
}

// Smallest eigenvector of symmetric 3x3 (analytic + one Rayleigh refinement).
__device__ __forceinline__ V3 smallest_evec(float a00, float a01, float a02,
                                            float a11, float a12, float a22){
    float m   = (a00 + a11 + a22) * (1.0f/3.0f);
    float b00 = a00 - m, b11 = a11 - m, b22 = a22 - m;
    float p1  = a01*a01 + a02*a02 + a12*a12;
    float p2  = b00*b00 + b11*b11 + b22*b22 + 2.0f*p1;
    float p   = sqrtf(fmaxf(p2*(1.0f/6.0f), 1e-30f));
    float invp = __fdividef(1.0f, p);
    float det = b00*(b11*b22 - a12*a12)
              - a01*(a01*b22 - a12*a02)
              + a02*(a01*a12 - b11*a02);
    float r = det * 0.5f * invp*invp*invp;
    r = fminf(fmaxf(r, -1.0f), 1.0f);
    float phi = acosf(r) * (1.0f/3.0f);
    float lam = m + 2.0f*p*cosf(phi + 2.0943951023931953f); // smallest eigenvalue

    V3 v;
    #pragma unroll
    for (int it = 0; it < 2; it++) {
        V3 r0 = { a00 - lam, a01, a02 };
        V3 r1 = { a01, a11 - lam, a12 };
        V3 r2 = { a02, a12, a22 - lam };
        V3 c0 = cross3(r0, r1), c1 = cross3(r0, r2), c2 = cross3(r1, r2);
        float l0 = dot3(c0,c0), l1 = dot3(c1,c1), l2 = dot3(c2,c2);
        V3 best = c0; float lb = l0;
        if (l1 > lb) { best = c1; lb = l1; }
        if (l2 > lb) { best = c2; lb = l2; }
        v = best * rsqrtf(fmaxf(lb, 1e-30f));
        if (it < 1) {
            float Av0 = a00*v.x + a01*v.y + a02*v.z;
            float Av1 = a01*v.x + a11*v.y + a12*v.z;
            float Av2 = a02*v.x + a12*v.y + a22*v.z;
            lam = v.x*Av0 + v.y*Av1 + v.z*Av2;
        }
    }
    return v;
}

// planarize one finger (4 joints via pointers, modified in place)
__device__ __forceinline__ void plan4(float* pM, float* pP, float* pD, float* pT){
    V3 p0 = ld3p(pM), p1 = ld3p(pP), p2 = ld3p(pD), p3 = ld3p(pT);
    V3 cm = (p0 + p1 + p2 + p3) * 0.25f;
    V3 d0 = p0 - cm, d1 = p1 - cm, d2 = p2 - cm, d3 = p3 - cm;
    float a00 = d0.x*d0.x + d1.x*d1.x + d2.x*d2.x + d3.x*d3.x;
    float a01 = d0.x*d0.y + d1.x*d1.y + d2.x*d2.y + d3.x*d3.y;
    float a02 = d0.x*d0.z + d1.x*d1.z + d2.x*d2.z + d3.x*d3.z;
    float a11 = d0.y*d0.y + d1.y*d1.y + d2.y*d2.y + d3.y*d3.y;
    float a12 = d0.y*d0.z + d1.y*d1.z + d2.y*d2.z + d3.y*d3.z;
    float a22 = d0.z*d0.z + d1.z*d1.z + d2.z*d2.z + d3.z*d3.z;
    V3 n = smallest_evec(a00, a01, a02, a11, a12, a22);
    float vd = -dot3(n, cm);
    float t;
    t = dot3(p0, n) + vd; st3p(pM, p0 - n*t);
    t = dot3(p1, n) + vd; st3p(pP, p1 - n*t);
    t = dot3(p2, n) + vd; st3p(pD, p2 - n*t);
    t = dot3(p3, n) + vd; st3p(pT, p3 - n*t);
}

// abduction for one finger
__device__ __forceinline__ void abduct(const float* pW, const float* pB,
                                       float rectC, float rectS,
                                       float* pM, float* pP, float* pD, float* pT){
    V3 w  = ld3p(pW);
    V3 mcp = ld3p(pM), pip = ld3p(pP);
    V3 pa = mcp - w, pb = ld3p(pB) - w;

    V3 palm = unitv(cross3(pa, pb));
    float vd   = -dot3(mcp, palm);
    float dist = dot3(pip, palm) + vd;
    V3 projpip = pip - palm*dist;

    V3 d  = pip - mcp;
    float dis = nrm3(d);
    float invdis = __fdividef(1.0f, dis + EPSF);
    V3 mcppip = d * invdis;

    V3 e  = projpip - mcp;
    float lene = nrm3(e);
    V3 mcpproj = e * __fdividef(1.0f, lene + EPSF);
    float flex = lene * invdis;
    flex = (flex < 0.3f) ? 0.0f : flex;

    V3 wristmcp = unitv(mcp - w);
    float cv = clampd(dot3(wristmcp, mcppip));
    bool overflex = cv < 0.00079632671073326f;   // == acos(cv) > 1.57

    // rect = R(palm, RECTIFY) * wristmcp  via vector Rodrigues (palm ~ unit)
    float Cr = 1.0f - rectC;
    V3 axw = cross3(palm, wristmcp);
    float adw = dot3(palm, wristmcp);
    V3 rect = wristmcp*rectC + axw*rectS + palm*(adw*Cr);

    float ang = acosf(clampd(dot3(rect, mcpproj)));
    if (overflex) ang = 0.0f;
    M3 R = getrot(ang, flex, palm, mcpproj, wristmcp);

    st3p(pP, mv(R, pip - mcp) + mcp);
    V3 c;
    c = ld3p(pD); st3p(pD, mv(R, c - mcp) + mcp);
    c = ld3p(pT); st3p(pT, mv(R, c - mcp) + mcp);
}

// plane rotation (flexRatio==1 -> analytic cos/sin of (a - pi/9), no acos/sincos)
__device__ __forceinline__ void planerot(const float* pW, const float* pB,
                                         float* pM, float* pP, float* pD, float* pT){
    const float COS_TH120 = -0.49999997f;      // cos(3.1415926/180*120)
    const float cAP = 0.93969262078590838f;    // cos(pi/9)
    const float sAP = 0.34202014332566871f;    // sin(pi/9)

    V3 w  = ld3p(pW);
    V3 mcp = ld3p(pM), pip = ld3p(pP), dip = ld3p(pD);
    V3 pa = mcp - w, pb = ld3p(pB) - w;

    V3 mcppip = unitv(pip - mcp);
    V3 pipdip = unitv(dip - pip);
    bool maskline = fabsf(dot3(mcppip, pipdip)) > 0.95f;
    V3 cdir = unitv(cross3(mcppip, pipdip));
    V3 palm = unitv(cross3(pa, pb));
    V3 stdv = unitv(cross3(unitv(mcp - w), palm));

    float x = clampd(dot3(cdir, stdv));
    float ca = (x < COS_TH120) ? -x : x;
    float sa = sqrtf(fmaxf(1.0f - x*x, 0.0f));
    if (maskline) { ca = 1.0f; sa = 0.0f; }

    float c, s;
    if (ca >= cAP) { c = 1.0f; s = 0.0f; }
    else { c = ca*cAP + sa*sAP; s = sa*cAP - ca*sAP; }
    M3 R = pick_rot(mcppip, c, s, cdir, stdv);

    st3p(pD, mv(R, dip - pip) + pip);
    V3 cc = ld3p(pT);
    st3p(pT, mv(R, cc - pip) + pip);
}

__global__ void __launch_bounds__(BLKT, 7)
handpose_kernel(const float* __restrict__ in, float* __restrict__ out, int N){
    __shared__ float s[HANDS * 63];
    int base = blockIdx.x * HANDS;
    int nE = N - base; if (nE > HANDS) nE = HANDS;
    int nF = nE * 63;
    const float* gin = in + (long long)base * 63;

    if (nE == HANDS) {
        const float4* g4 = (const float4*)gin;   // base*63*4 B divisible by 16
        float4* s4 = (float4*)s;
        for (int k = threadIdx.x; k < (HANDS*63)/4; k += BLKT)
            s4[k] = g4[k];
    } else {
        for (int k = threadIdx.x; k < nF; k += BLKT) s[k] = gin[k];
    }
    __syncthreads();

    int lane = threadIdx.x & 31;   // hand within block
    int f    = threadIdx.x >> 5;   // finger (uniform per warp)
    bool act = lane < nE;
    float* sp = s + lane * 63;

    // per-finger joint pointers (computed once; all later accesses use imm offsets)
    int imcp = cMCP[f];
    bool thumb = (f == 4);
    float* pW = sp;
    float* pM = sp + 3*imcp;
    float* pP = pM + 3;                    // PIP = MCP+1 for all fingers
    float* pD = pM + 6;                    // DIP = MCP+2
    float* pT = sp + 3*(thumb ? 16 : 13 + imcp + imcp/4); // TIP: 17,18,19,20 / 16
    // fingers 0..3: mcp 1,4,10,7 -> tip 17,18,19,20. Compute via table-free map:
    // mcp1->17, mcp4->18, mcp10->19, mcp7->20. (1,4,10,7)+... not linear; use constant:
    // handled below instead.
    {
        // small warp-uniform table lookup kept in registers
        const int tips[5] = {17, 18, 19, 20, 16};
        pT = sp + 3*tips[f];
    }
    float* pB = sp + 3*cPB[f];
    float rc = cRC[f], rs = cRS[f];

    // ---- planarize #1 (all fingers parallel, one shared code path) ----
    if (act) plan4(pM, pP, pD, pT);
    __syncthreads();   // abduction reads neighbor MCPs written above

    if (act) {
        // ---- abduction ----
        abduct(pW, pB, rc, rs, pM, pP, pD, pT);
        // ---- plane rotation (fingers 0..3; warp-uniform predicate) ----
        if (!thumb) planerot(pW, pB, pM, pP, pD, pT);
        // ---- planarize #2 ----
        plan4(pM, pP, pD, pT);
    }
    __syncthreads();

    float* gout = out + (long long)base * 63;
    if (nE == HANDS) {
        const float4* s4 = (const float4*)s;
        float4* g4 = (float4*)gout;
        for (int k = threadIdx.x; k < (HANDS*63)/4; k += BLKT)
            g4[k] = s4[k];
    } else {
        for (int k = threadIdx.x; k < nF; k += BLKT) gout[k] = s[k];
    }
}

extern "C" void kernel_launch(void* const* d_in, const int* in_sizes, int n_in,
                              void* d_out, int out_size){
    const float* in = (const float*)d_in[0];
    float* out = (float*)d_out;
    int N = in_sizes[0] / 63;
    int grid = (N + HANDS - 1) / HANDS;
    handpose_kernel<<<grid, BLKT>>>(in, out, N);
}

// round 8
// speedup vs baseline: 1.6899x; 1.0356x over previous
#include <cuda_runtime.h>
#include <math.h>

#define EPSF 1e-6f
#define HANDS 32
#define BLKT 160   // 32 hands x 5 finger-warps

struct V3 { float x, y, z; };

__device__ __forceinline__ V3 operator+(V3 a, V3 b){ return {a.x+b.x, a.y+b.y, a.z+b.z}; }
__device__ __forceinline__ V3 operator-(V3 a, V3 b){ return {a.x-b.x, a.y-b.y, a.z-b.z}; }
__device__ __forceinline__ V3 operator*(V3 a, float s){ return {a.x*s, a.y*s, a.z*s}; }
__device__ __forceinline__ float dot3(V3 a, V3 b){ return a.x*b.x + a.y*b.y + a.z*b.z; }
__device__ __forceinline__ V3 cross3(V3 a, V3 b){
    return { a.y*b.z - a.z*b.y, a.z*b.x - a.x*b.z, a.x*b.y - a.y*b.x };
}
__device__ __forceinline__ float nrm3(V3 a){ return sqrtf(dot3(a,a)); }
__device__ __forceinline__ V3 unitv(V3 a){
    float inv = __fdividef(1.0f, nrm3(a)+EPSF); return a*inv;
}
__device__ __forceinline__ float clampd(float x){ return fminf(fmaxf(x, -1.0f+EPSF), 1.0f-EPSF); }

struct M3 { float a[9]; };

__device__ __forceinline__ V3 mv(const M3& R, V3 v){
    return { R.a[0]*v.x + R.a[1]*v.y + R.a[2]*v.z,
             R.a[3]*v.x + R.a[4]*v.y + R.a[5]*v.z,
             R.a[6]*v.x + R.a[7]*v.y + R.a[8]*v.z };
}

__device__ __forceinline__ V3 ld3p(const float* p){ return { p[0], p[1], p[2] }; }
__device__ __forceinline__ void st3p(float* p, V3 v){ p[0] = v.x; p[1] = v.y; p[2] = v.z; }

// per-finger tables
__constant__ int   cMCP[5] = {1, 4, 10, 7, 13};
__constant__ int   cTIP[5] = {17, 18, 19, 20, 16};
__constant__ int   cPB [5] = {4, 10, 7, 1, 1};           // palm b index (a index == MCP)
__constant__ float cRC [5] = {0.98219268f, 0.99115533f, 0.98890531f, 0.99939799f, 1.0f};
__constant__ float cRS [5] = {0.18787768f, 0.13270742f, -0.14855814f, 0.03469304f, 0.0f};

// Rodrigues matrix from UNIT axis
__device__ __forceinline__ M3 rotmat_u(V3 a, float c, float s){
    float C = 1.0f - c;
    M3 R;
    R.a[0] = c + a.x*a.x*C;     R.a[1] = a.x*a.y*C - a.z*s; R.a[2] = a.x*a.z*C + a.y*s;
    R.a[3] = a.y*a.x*C + a.z*s; R.a[4] = c + a.y*a.y*C;     R.a[5] = a.y*a.z*C - a.x*s;
    R.a[6] = a.z*a.x*C - a.y*s; R.a[7] = a.z*a.y*C + a.x*s; R.a[8] = c + a.z*a.z*C;
    return R;
}

// Sign-resolved rotation: d0=(R(+)sv)·ev = t1+t2 ; d1=(R(-)sv)·ev = t1-t2.
// |d0|>|d1| <=> t1*t2>0 ; reference picks R(-) on tie.
__device__ __forceinline__ M3 pick_rot(V3 a, float c, float s, V3 sv, V3 ev){
    float C  = 1.0f - c;
    float t1 = c*dot3(sv, ev) + C*dot3(a, sv)*dot3(a, ev);
    float t2 = s*dot3(cross3(a, sv), ev);
    if (!(t1*t2 > 0.0f)) s = -s;
    return rotmat_u(a, c, s);
}

// getrot for abduction (angle scaled by flexRatio -> real sincos)
__device__ __forceinline__ M3 getrot(float angle, float flexRatio, V3 axisU, V3 sv, V3 ev){
    const float ANGLEP = 0.34906585039886590f;  // pi/9
    const float TH120  = 2.09439506666666650f;  // 3.1415926/180*120
    angle = (angle > TH120) ? (3.1415926f - angle) : angle;
    float dif = fmaxf(angle - ANGLEP, 0.0f) * flexRatio;
    float s, c;
    sincosf(dif, &s, &c);
    return pick_rot(axisU, c, s, sv, ev);
}

// Smallest eigenvector of symmetric 3x3 (analytic + one Rayleigh refinement).
__device__ __forceinline__ V3 smallest_evec(float a00, float a01, float a02,
                                            float a11, float a12, float a22){
    float m   = (a00 + a11 + a22) * (1.0f/3.0f);
    float b00 = a00 - m, b11 = a11 - m, b22 = a22 - m;
    float p1  = a01*a01 + a02*a02 + a12*a12;
    float p2  = b00*b00 + b11*b11 + b22*b22 + 2.0f*p1;
    float p   = sqrtf(fmaxf(p2*(1.0f/6.0f), 1e-30f));
    float invp = __fdividef(1.0f, p);
    float det = b00*(b11*b22 - a12*a12)
              - a01*(a01*b22 - a12*a02)
              + a02*(a01*a12 - b11*a02);
    float r = det * 0.5f * invp*invp*invp;
    r = fminf(fmaxf(r, -1.0f), 1.0f);
    float phi = acosf(r) * (1.0f/3.0f);
    float lam = m + 2.0f*p*cosf(phi + 2.0943951023931953f); // smallest eigenvalue

    V3 v;
    #pragma unroll
    for (int it = 0; it < 2; it++) {
        V3 r0 = { a00 - lam, a01, a02 };
        V3 r1 = { a01, a11 - lam, a12 };
        V3 r2 = { a02, a12, a22 - lam };
        V3 c0 = cross3(r0, r1), c1 = cross3(r0, r2), c2 = cross3(r1, r2);
        float l0 = dot3(c0,c0), l1 = dot3(c1,c1), l2 = dot3(c2,c2);
        V3 best = c0; float lb = l0;
        if (l1 > lb) { best = c1; lb = l1; }
        if (l2 > lb) { best = c2; lb = l2; }
        v = best * rsqrtf(fmaxf(lb, 1e-30f));
        if (it < 1) {
            float Av0 = a00*v.x + a01*v.y + a02*v.z;
            float Av1 = a01*v.x + a11*v.y + a12*v.z;
            float Av2 = a02*v.x + a12*v.y + a22*v.z;
            lam = v.x*Av0 + v.y*Av1 + v.z*Av2;
        }
    }
    return v;
}

// planarize one finger (register-resident)
__device__ __forceinline__ void plan4(V3& p0, V3& p1, V3& p2, V3& p3){
    V3 cm = (p0 + p1 + p2 + p3) * 0.25f;
    V3 d0 = p0 - cm, d1 = p1 - cm, d2 = p2 - cm, d3 = p3 - cm;
    float a00 = d0.x*d0.x + d1.x*d1.x + d2.x*d2.x + d3.x*d3.x;
    float a01 = d0.x*d0.y + d1.x*d1.y + d2.x*d2.y + d3.x*d3.y;
    float a02 = d0.x*d0.z + d1.x*d1.z + d2.x*d2.z + d3.x*d3.z;
    float a11 = d0.y*d0.y + d1.y*d1.y + d2.y*d2.y + d3.y*d3.y;
    float a12 = d0.y*d0.z + d1.y*d1.z + d2.y*d2.z + d3.y*d3.z;
    float a22 = d0.z*d0.z + d1.z*d1.z + d2.z*d2.z + d3.z*d3.z;
    V3 n = smallest_evec(a00, a01, a02, a11, a12, a22);
    float vd = -dot3(n, cm);
    float t;
    t = dot3(p0, n) + vd; p0 = p0 - n*t;
    t = dot3(p1, n) + vd; p1 = p1 - n*t;
    t = dot3(p2, n) + vd; p2 = p2 - n*t;
    t = dot3(p3, n) + vd; p3 = p3 - n*t;
}

// abduction (register-resident; pbv = neighbor MCP post-planarize)
__device__ __forceinline__ void abduct(V3 w, V3 pbv, float rectC, float rectS,
                                       V3 mcp, V3& pip, V3& dip, V3& tip){
    V3 pa = mcp - w, pb = pbv - w;

    V3 palm = unitv(cross3(pa, pb));
    float vd   = -dot3(mcp, palm);
    float dist = dot3(pip, palm) + vd;
    V3 projpip = pip - palm*dist;

    V3 d  = pip - mcp;
    float dis = nrm3(d);
    float invdis = __fdividef(1.0f, dis + EPSF);
    V3 mcppip = d * invdis;

    V3 e  = projpip - mcp;
    float lene = nrm3(e);
    V3 mcpproj = e * __fdividef(1.0f, lene + EPSF);
    float flex = lene * invdis;
    flex = (flex < 0.3f) ? 0.0f : flex;

    V3 wristmcp = unitv(mcp - w);
    float cv = clampd(dot3(wristmcp, mcppip));
    bool overflex = cv < 0.00079632671073326f;   // == acos(cv) > 1.57

    // rect = R(palm, RECTIFY) * wristmcp  via vector Rodrigues (palm ~ unit)
    float Cr = 1.0f - rectC;
    V3 axw = cross3(palm, wristmcp);
    float adw = dot3(palm, wristmcp);
    V3 rect = wristmcp*rectC + axw*rectS + palm*(adw*Cr);

    float ang = acosf(clampd(dot3(rect, mcpproj)));
    if (overflex) ang = 0.0f;
    M3 R = getrot(ang, flex, palm, mcpproj, wristmcp);

    pip = mv(R, pip - mcp) + mcp;
    dip = mv(R, dip - mcp) + mcp;
    tip = mv(R, tip - mcp) + mcp;
}

// plane rotation (register-resident; analytic cos/sin of (a - pi/9))
__device__ __forceinline__ void planerot(V3 w, V3 pbv,
                                         V3 mcp, V3 pip, V3& dip, V3& tip){
    const float COS_TH120 = -0.49999997f;      // cos(3.1415926/180*120)
    const float cAP = 0.93969262078590838f;    // cos(pi/9)
    const float sAP = 0.34202014332566871f;    // sin(pi/9)

    V3 pa = mcp - w, pb = pbv - w;

    V3 mcppip = unitv(pip - mcp);
    V3 pipdip = unitv(dip - pip);
    bool maskline = fabsf(dot3(mcppip, pipdip)) > 0.95f;
    V3 cdir = unitv(cross3(mcppip, pipdip));
    V3 palm = unitv(cross3(pa, pb));
    V3 stdv = unitv(cross3(unitv(mcp - w), palm));

    float x = clampd(dot3(cdir, stdv));
    float ca = (x < COS_TH120) ? -x : x;
    float sa = sqrtf(fmaxf(1.0f - x*x, 0.0f));
    if (maskline) { ca = 1.0f; sa = 0.0f; }

    float c, s;
    if (ca >= cAP) { c = 1.0f; s = 0.0f; }
    else { c = ca*cAP + sa*sAP; s = sa*cAP - ca*sAP; }
    M3 R = pick_rot(mcppip, c, s, cdir, stdv);

    dip = mv(R, dip - pip) + pip;
    tip = mv(R, tip - pip) + pip;
}

__global__ void __launch_bounds__(BLKT, 6)
handpose_kernel(const float* __restrict__ in, float* __restrict__ out, int N){
    __shared__ float s[HANDS * 63];
    int base = blockIdx.x * HANDS;
    int nE = N - base; if (nE > HANDS) nE = HANDS;
    int nF = nE * 63;
    const float* gin = in + (long long)base * 63;

    if (nE == HANDS) {
        const float4* g4 = (const float4*)gin;   // base*63*4 B divisible by 16
        float4* s4 = (float4*)s;
        for (int k = threadIdx.x; k < (HANDS*63)/4; k += BLKT)
            s4[k] = g4[k];
    } else {
        for (int k = threadIdx.x; k < nF; k += BLKT) s[k] = gin[k];
    }
    __syncthreads();

    int lane = threadIdx.x & 31;   // hand within block
    int f    = threadIdx.x >> 5;   // finger (uniform per warp)
    bool act = lane < nE;
    bool thumb = (f == 4);
    float* sp = s + lane * 63;

    float* pM = sp + 3*cMCP[f];
    float* pT = sp + 3*cTIP[f];
    float* pB = sp + 3*cPB[f];
    float rc = cRC[f], rs = cRS[f];

    V3 w, mcp, pip, dip, tip;
    if (act) {
        w   = ld3p(sp);
        mcp = ld3p(pM);
        pip = ld3p(pM + 3);
        dip = ld3p(pM + 6);
        tip = ld3p(pT);

        // ---- planarize #1 (registers) ----
        plan4(mcp, pip, dip, tip);
        st3p(pM, mcp);   // publish planarized MCP for neighbor warps
    }
    __syncthreads();

    if (act) {
        V3 pbv = ld3p(pB);    // neighbor MCP (post-plan#1; unchanged by abduction)

        // ---- abduction ----
        abduct(w, pbv, rc, rs, mcp, pip, dip, tip);
        // ---- plane rotation (fingers 0..3) ----
        if (!thumb) planerot(w, pbv, mcp, pip, dip, tip);
        // ---- planarize #2 ----
        plan4(mcp, pip, dip, tip);

        st3p(pM,     mcp);
        st3p(pM + 3, pip);
        st3p(pM + 6, dip);
        st3p(pT,     tip);
    }
    __syncthreads();

    float* gout = out + (long long)base * 63;
    if (nE == HANDS) {
        const float4* s4 = (const float4*)s;
        float4* g4 = (float4*)gout;
        for (int k = threadIdx.x; k < (HANDS*63)/4; k += BLKT)
            g4[k] = s4[k];
    } else {
        for (int k = threadIdx.x; k < nF; k += BLKT) gout[k] = s[k];
    }
}

extern "C" void kernel_launch(void* const* d_in, const int* in_sizes, int n_in,
                              void* d_out, int out_size){
    const float* in = (const float*)d_in[0];
    float* out = (float*)d_out;
    int N = in_sizes[0] / 63;
    int grid = (N + HANDS - 1) / HANDS;
    handpose_kernel<<<grid, BLKT>>>(in, out, N);
}

// round 9
// speedup vs baseline: 1.9598x; 1.1597x over previous
#include <cuda_runtime.h>
#include <math.h>

#define EPSF 1e-6f
#define HANDS 32
#define BLKT 160   // 32 hands x 5 finger-warps

struct V3 { float x, y, z; };

__device__ __forceinline__ V3 operator+(V3 a, V3 b){ return {a.x+b.x, a.y+b.y, a.z+b.z}; }
__device__ __forceinline__ V3 operator-(V3 a, V3 b){ return {a.x-b.x, a.y-b.y, a.z-b.z}; }
__device__ __forceinline__ V3 operator*(V3 a, float s){ return {a.x*s, a.y*s, a.z*s}; }
__device__ __forceinline__ float dot3(V3 a, V3 b){ return a.x*b.x + a.y*b.y + a.z*b.z; }
__device__ __forceinline__ V3 cross3(V3 a, V3 b){
    return { a.y*b.z - a.z*b.y, a.z*b.x - a.x*b.z, a.x*b.y - a.y*b.x };
}
__device__ __forceinline__ float nrm3(V3 a){ return sqrtf(dot3(a,a)); }
__device__ __forceinline__ V3 unitv(V3 a){
    float inv = __fdividef(1.0f, nrm3(a)+EPSF); return a*inv;
}
__device__ __forceinline__ float clampd(float x){ return fminf(fmaxf(x, -1.0f+EPSF), 1.0f-EPSF); }

struct M3 { float a[9]; };

__device__ __forceinline__ V3 mv(const M3& R, V3 v){
    return { R.a[0]*v.x + R.a[1]*v.y + R.a[2]*v.z,
             R.a[3]*v.x + R.a[4]*v.y + R.a[5]*v.z,
             R.a[6]*v.x + R.a[7]*v.y + R.a[8]*v.z };
}

__device__ __forceinline__ V3 ld3p(const float* p){ return { p[0], p[1], p[2] }; }
__device__ __forceinline__ void st3p(float* p, V3 v){ p[0] = v.x; p[1] = v.y; p[2] = v.z; }

// per-finger tables
__constant__ int   cMCP[5] = {1, 4, 10, 7, 13};
__constant__ int   cTIP[5] = {17, 18, 19, 20, 16};
__constant__ int   cPB [5] = {4, 10, 7, 1, 1};           // palm b index (a index == MCP)
__constant__ float cRC [5] = {0.98219268f, 0.99115533f, 0.98890531f, 0.99939799f, 1.0f};
__constant__ float cRS [5] = {0.18787768f, 0.13270742f, -0.14855814f, 0.03469304f, 0.0f};

// Rodrigues matrix from UNIT axis
__device__ __forceinline__ M3 rotmat_u(V3 a, float c, float s){
    float C = 1.0f - c;
    M3 R;
    R.a[0] = c + a.x*a.x*C;     R.a[1] = a.x*a.y*C - a.z*s; R.a[2] = a.x*a.z*C + a.y*s;
    R.a[3] = a.y*a.x*C + a.z*s; R.a[4] = c + a.y*a.y*C;     R.a[5] = a.y*a.z*C - a.x*s;
    R.a[6] = a.z*a.x*C - a.y*s; R.a[7] = a.z*a.y*C + a.x*s; R.a[8] = c + a.z*a.z*C;
    return R;
}

// Sign-resolved rotation: d0=(R(+)sv)·ev = t1+t2 ; d1=(R(-)sv)·ev = t1-t2.
// |d0|>|d1| <=> t1*t2>0 ; reference picks R(-) on tie.
__device__ __forceinline__ M3 pick_rot(V3 a, float c, float s, V3 sv, V3 ev){
    float C  = 1.0f - c;
    float t1 = c*dot3(sv, ev) + C*dot3(a, sv)*dot3(a, ev);
    float t2 = s*dot3(cross3(a, sv), ev);
    if (!(t1*t2 > 0.0f)) s = -s;
    return rotmat_u(a, c, s);
}

// getrot for abduction (angle scaled by flexRatio -> real sincos)
__device__ __forceinline__ M3 getrot(float angle, float flexRatio, V3 axisU, V3 sv, V3 ev){
    const float ANGLEP = 0.34906585039886590f;  // pi/9
    const float TH120  = 2.09439506666666650f;  // 3.1415926/180*120
    angle = (angle > TH120) ? (3.1415926f - angle) : angle;
    float dif = fmaxf(angle - ANGLEP, 0.0f) * flexRatio;
    float s, c;
    sincosf(dif, &s, &c);
    return pick_rot(axisU, c, s, sv, ev);
}

// Smallest eigenvector of symmetric 3x3 (analytic + one Rayleigh refinement).
__device__ __forceinline__ V3 smallest_evec(float a00, float a01, float a02,
                                            float a11, float a12, float a22){
    float m   = (a00 + a11 + a22) * (1.0f/3.0f);
    float b00 = a00 - m, b11 = a11 - m, b22 = a22 - m;
    float p1  = a01*a01 + a02*a02 + a12*a12;
    float p2  = b00*b00 + b11*b11 + b22*b22 + 2.0f*p1;
    float p   = sqrtf(fmaxf(p2*(1.0f/6.0f), 1e-30f));
    float invp = __fdividef(1.0f, p);
    float det = b00*(b11*b22 - a12*a12)
              - a01*(a01*b22 - a12*a02)
              + a02*(a01*a12 - b11*a02);
    float r = det * 0.5f * invp*invp*invp;
    r = fminf(fmaxf(r, -1.0f), 1.0f);
    float phi = acosf(r) * (1.0f/3.0f);
    float lam = m + 2.0f*p*cosf(phi + 2.0943951023931953f); // smallest eigenvalue

    V3 v;
    #pragma unroll
    for (int it = 0; it < 2; it++) {
        V3 r0 = { a00 - lam, a01, a02 };
        V3 r1 = { a01, a11 - lam, a12 };
        V3 r2 = { a02, a12, a22 - lam };
        V3 c0 = cross3(r0, r1), c1 = cross3(r0, r2), c2 = cross3(r1, r2);
        float l0 = dot3(c0,c0), l1 = dot3(c1,c1), l2 = dot3(c2,c2);
        V3 best = c0; float lb = l0;
        if (l1 > lb) { best = c1; lb = l1; }
        if (l2 > lb) { best = c2; lb = l2; }
        v = best * rsqrtf(fmaxf(lb, 1e-30f));
        if (it < 1) {
            float Av0 = a00*v.x + a01*v.y + a02*v.z;
            float Av1 = a01*v.x + a11*v.y + a12*v.z;
            float Av2 = a02*v.x + a12*v.y + a22*v.z;
            lam = v.x*Av0 + v.y*Av1 + v.z*Av2;
        }
    }
    return v;
}

// planarize one finger (register-resident)
__device__ __forceinline__ void plan4(V3& p0, V3& p1, V3& p2, V3& p3){
    V3 cm = (p0 + p1 + p2 + p3) * 0.25f;
    V3 d0 = p0 - cm, d1 = p1 - cm, d2 = p2 - cm, d3 = p3 - cm;
    float a00 = d0.x*d0.x + d1.x*d1.x + d2.x*d2.x + d3.x*d3.x;
    float a01 = d0.x*d0.y + d1.x*d1.y + d2.x*d2.y + d3.x*d3.y;
    float a02 = d0.x*d0.z + d1.x*d1.z + d2.x*d2.z + d3.x*d3.z;
    float a11 = d0.y*d0.y + d1.y*d1.y + d2.y*d2.y + d3.y*d3.y;
    float a12 = d0.y*d0.z + d1.y*d1.z + d2.y*d2.z + d3.y*d3.z;
    float a22 = d0.z*d0.z + d1.z*d1.z + d2.z*d2.z + d3.z*d3.z;
    V3 n = smallest_evec(a00, a01, a02, a11, a12, a22);
    float vd = -dot3(n, cm);
    float t;
    t = dot3(p0, n) + vd; p0 = p0 - n*t;
    t = dot3(p1, n) + vd; p1 = p1 - n*t;
    t = dot3(p2, n) + vd; p2 = p2 - n*t;
    t = dot3(p3, n) + vd; p3 = p3 - n*t;
}

// abduction (register-resident; pbv = neighbor MCP post-planarize)
__device__ __forceinline__ void abduct(V3 w, V3 pbv, float rectC, float rectS,
                                       V3 mcp, V3& pip, V3& dip, V3& tip){
    V3 pa = mcp - w, pb = pbv - w;

    V3 palm = unitv(cross3(pa, pb));
    float vd   = -dot3(mcp, palm);
    float dist = dot3(pip, palm) + vd;
    V3 projpip = pip - palm*dist;

    V3 d  = pip - mcp;
    float dis = nrm3(d);
    float invdis = __fdividef(1.0f, dis + EPSF);
    V3 mcppip = d * invdis;

    V3 e  = projpip - mcp;
    float lene = nrm3(e);
    V3 mcpproj = e * __fdividef(1.0f, lene + EPSF);
    float flex = lene * invdis;
    flex = (flex < 0.3f) ? 0.0f : flex;

    V3 wristmcp = unitv(mcp - w);
    float cv = clampd(dot3(wristmcp, mcppip));
    bool overflex = cv < 0.00079632671073326f;   // == acos(cv) > 1.57

    // rect = R(palm, RECTIFY) * wristmcp  via vector Rodrigues (palm ~ unit)
    float Cr = 1.0f - rectC;
    V3 axw = cross3(palm, wristmcp);
    float adw = dot3(palm, wristmcp);
    V3 rect = wristmcp*rectC + axw*rectS + palm*(adw*Cr);

    float ang = acosf(clampd(dot3(rect, mcpproj)));
    if (overflex) ang = 0.0f;
    M3 R = getrot(ang, flex, palm, mcpproj, wristmcp);

    pip = mv(R, pip - mcp) + mcp;
    dip = mv(R, dip - mcp) + mcp;
    tip = mv(R, tip - mcp) + mcp;
}

// plane rotation (register-resident; analytic cos/sin of (a - pi/9))
__device__ __forceinline__ void planerot(V3 w, V3 pbv,
                                         V3 mcp, V3 pip, V3& dip, V3& tip){
    const float COS_TH120 = -0.49999997f;      // cos(3.1415926/180*120)
    const float cAP = 0.93969262078590838f;    // cos(pi/9)
    const float sAP = 0.34202014332566871f;    // sin(pi/9)

    V3 pa = mcp - w, pb = pbv - w;

    V3 mcppip = unitv(pip - mcp);
    V3 pipdip = unitv(dip - pip);
    bool maskline = fabsf(dot3(mcppip, pipdip)) > 0.95f;
    V3 cdir = unitv(cross3(mcppip, pipdip));
    V3 palm = unitv(cross3(pa, pb));
    V3 stdv = unitv(cross3(unitv(mcp - w), palm));

    float x = clampd(dot3(cdir, stdv));
    float ca = (x < COS_TH120) ? -x : x;
    float sa = sqrtf(fmaxf(1.0f - x*x, 0.0f));
    if (maskline) { ca = 1.0f; sa = 0.0f; }

    float c, s;
    if (ca >= cAP) { c = 1.0f; s = 0.0f; }
    else { c = ca*cAP + sa*sAP; s = sa*cAP - ca*sAP; }
    M3 R = pick_rot(mcppip, c, s, cdir, stdv);

    dip = mv(R, dip - pip) + pip;
    tip = mv(R, tip - pip) + pip;
}

__global__ void __launch_bounds__(BLKT, 7)
handpose_kernel(const float* __restrict__ in, float* __restrict__ out, int N){
    __shared__ float s[HANDS * 63];
    int base = blockIdx.x * HANDS;
    int nE = N - base; if (nE > HANDS) nE = HANDS;
    int nF = nE * 63;
    const float* gin = in + (long long)base * 63;

    if (nE == HANDS) {
        const float4* g4 = (const float4*)gin;   // base*63*4 B divisible by 16
        float4* s4 = (float4*)s;
        for (int k = threadIdx.x; k < (HANDS*63)/4; k += BLKT)
            s4[k] = g4[k];
    } else {
        for (int k = threadIdx.x; k < nF; k += BLKT) s[k] = gin[k];
    }
    __syncthreads();

    int lane = threadIdx.x & 31;   // hand within block
    int f    = threadIdx.x >> 5;   // finger (uniform per warp)
    bool act = lane < nE;
    bool thumb = (f == 4);
    float* sp = s + lane * 63;

    float* pM = sp + 3*cMCP[f];
    float* pT = sp + 3*cTIP[f];
    float* pB = sp + 3*cPB[f];
    float rc = cRC[f], rs = cRS[f];

    V3 w, mcp, pip, dip, tip;
    if (act) {
        w   = ld3p(sp);
        mcp = ld3p(pM);
        pip = ld3p(pM + 3);
        dip = ld3p(pM + 6);
        tip = ld3p(pT);

        // ---- planarize #1 (registers) ----
        plan4(mcp, pip, dip, tip);
        st3p(pM, mcp);   // publish planarized MCP for neighbor warps
    }
    __syncthreads();

    if (act) {
        V3 pbv = ld3p(pB);    // neighbor MCP (post-plan#1; unchanged by abduction)

        // ---- abduction ----
        abduct(w, pbv, rc, rs, mcp, pip, dip, tip);
        // ---- plane rotation (fingers 0..3) ----
        if (!thumb) planerot(w, pbv, mcp, pip, dip, tip);

        // ---- planarize #2 is a provable no-op: the 4 joints are exactly
        // coplanar after plan#1 + rigid rotations whose fixed points / axes
        // lie in the plane (see derivation); projecting coplanar points onto
        // their own plane changes nothing beyond fp epsilon (~1e-7). ----

        st3p(pM,     mcp);
        st3p(pM + 3, pip);
        st3p(pM + 6, dip);
        st3p(pT,     tip);
    }
    __syncthreads();

    float* gout = out + (long long)base * 63;
    if (nE == HANDS) {
        const float4* s4 = (const float4*)s;
        float4* g4 = (float4*)gout;
        for (int k = threadIdx.x; k < (HANDS*63)/4; k += BLKT)
            g4[k] = s4[k];
    } else {
        for (int k = threadIdx.x; k < nF; k += BLKT) gout[k] = s[k];
    }
}

extern "C" void kernel_launch(void* const* d_in, const int* in_sizes, int n_in,
                              void* d_out, int out_size){
    const float* in = (const float*)d_in[0];
    float* out = (float*)d_out;
    int N = in_sizes[0] / 63;
    int grid = (N + HANDS - 1) / HANDS;
    handpose_kernel<<<grid, BLKT>>>(in, out, N);
}

// round 11
// speedup vs baseline: 1.9656x; 1.0030x over previous
#include <cuda_runtime.h>
#include <math.h>

#define EPSF 1e-6f
#define HANDS 32
#define BLKT 160   // 32 hands x 5 finger-warps

struct V3 { float x, y, z; };

__device__ __forceinline__ V3 operator+(V3 a, V3 b){ return {a.x+b.x, a.y+b.y, a.z+b.z}; }
__device__ __forceinline__ V3 operator-(V3 a, V3 b){ return {a.x-b.x, a.y-b.y, a.z-b.z}; }
__device__ __forceinline__ V3 operator*(V3 a, float s){ return {a.x*s, a.y*s, a.z*s}; }
__device__ __forceinline__ float dot3(V3 a, V3 b){ return a.x*b.x + a.y*b.y + a.z*b.z; }
__device__ __forceinline__ V3 cross3(V3 a, V3 b){
    return { a.y*b.z - a.z*b.y, a.z*b.x - a.x*b.z, a.x*b.y - a.y*b.x };
}
__device__ __forceinline__ float nrm3(V3 a){ return sqrtf(dot3(a,a)); }
// EXACT reference semantics: v / (|v| + 1e-6). The additive epsilon is
// load-bearing for near-degenerate cross products — do NOT replace with rsqrt.
__device__ __forceinline__ V3 unitv(V3 a){
    float inv = __fdividef(1.0f, nrm3(a)+EPSF); return a*inv;
}
__device__ __forceinline__ float clampd(float x){ return fminf(fmaxf(x, -1.0f+EPSF), 1.0f-EPSF); }

struct M3 { float a[9]; };

__device__ __forceinline__ V3 mv(const M3& R, V3 v){
    return { R.a[0]*v.x + R.a[1]*v.y + R.a[2]*v.z,
             R.a[3]*v.x + R.a[4]*v.y + R.a[5]*v.z,
             R.a[6]*v.x + R.a[7]*v.y + R.a[8]*v.z };
}

__device__ __forceinline__ V3 ld3p(const float* p){ return { p[0], p[1], p[2] }; }
__device__ __forceinline__ void st3p(float* p, V3 v){ p[0] = v.x; p[1] = v.y; p[2] = v.z; }

// per-finger tables
__constant__ int   cMCP[5] = {1, 4, 10, 7, 13};
__constant__ int   cTIP[5] = {17, 18, 19, 20, 16};
__constant__ int   cPB [5] = {4, 10, 7, 1, 1};           // palm b index (a index == MCP)
__constant__ float cRC [5] = {0.98219268f, 0.99115533f, 0.98890531f, 0.99939799f, 1.0f};
__constant__ float cRS [5] = {0.18787768f, 0.13270742f, -0.14855814f, 0.03469304f, 0.0f};

// Rodrigues matrix from UNIT axis
__device__ __forceinline__ M3 rotmat_u(V3 a, float c, float s){
    float C = 1.0f - c;
    M3 R;
    R.a[0] = c + a.x*a.x*C;     R.a[1] = a.x*a.y*C - a.z*s; R.a[2] = a.x*a.z*C + a.y*s;
    R.a[3] = a.y*a.x*C + a.z*s; R.a[4] = c + a.y*a.y*C;     R.a[5] = a.y*a.z*C - a.x*s;
    R.a[6] = a.z*a.x*C - a.y*s; R.a[7] = a.z*a.y*C + a.x*s; R.a[8] = c + a.z*a.z*C;
    return R;
}

// Sign-resolved rotation: d0=(R(+)sv)·ev = t1+t2 ; d1=(R(-)sv)·ev = t1-t2.
// |d0|>|d1| <=> t1*t2>0 ; reference picks R(-) on tie.
__device__ __forceinline__ M3 pick_rot(V3 a, float c, float s, V3 sv, V3 ev){
    float C  = 1.0f - c;
    float t1 = c*dot3(sv, ev) + C*dot3(a, sv)*dot3(a, ev);
    float t2 = s*dot3(cross3(a, sv), ev);
    if (!(t1*t2 > 0.0f)) s = -s;
    return rotmat_u(a, c, s);
}

// getrot for abduction (angle scaled by flexRatio -> real sincos)
__device__ __forceinline__ M3 getrot(float angle, float flexRatio, V3 axisU, V3 sv, V3 ev){
    const float ANGLEP = 0.34906585039886590f;  // pi/9
    const float TH120  = 2.09439506666666650f;  // 3.1415926/180*120
    angle = (angle > TH120) ? (3.1415926f - angle) : angle;
    float dif = fmaxf(angle - ANGLEP, 0.0f) * flexRatio;
    float s, c;
    sincosf(dif, &s, &c);
    return pick_rot(axisU, c, s, sv, ev);
}

// Smallest eigenvector of symmetric 3x3 (analytic + one Rayleigh refinement).
__device__ __forceinline__ V3 smallest_evec(float a00, float a01, float a02,
                                            float a11, float a12, float a22){
    float m   = (a00 + a11 + a22) * (1.0f/3.0f);
    float b00 = a00 - m, b11 = a11 - m, b22 = a22 - m;
    float p1  = a01*a01 + a02*a02 + a12*a12;
    float p2  = b00*b00 + b11*b11 + b22*b22 + 2.0f*p1;
    float p   = sqrtf(fmaxf(p2*(1.0f/6.0f), 1e-30f));
    float invp = __fdividef(1.0f, p);
    float det = b00*(b11*b22 - a12*a12)
              - a01*(a01*b22 - a12*a02)
              + a02*(a01*a12 - b11*a02);
    float r = det * 0.5f * invp*invp*invp;
    r = fminf(fmaxf(r, -1.0f), 1.0f);
    float phi = acosf(r) * (1.0f/3.0f);
    float lam = m + 2.0f*p*cosf(phi + 2.0943951023931953f); // smallest eigenvalue

    V3 v;
    #pragma unroll
    for (int it = 0; it < 2; it++) {
        V3 r0 = { a00 - lam, a01, a02 };
        V3 r1 = { a01, a11 - lam, a12 };
        V3 r2 = { a02, a12, a22 - lam };
        V3 c0 = cross3(r0, r1), c1 = cross3(r0, r2), c2 = cross3(r1, r2);
        float l0 = dot3(c0,c0), l1 = dot3(c1,c1), l2 = dot3(c2,c2);
        V3 best = c0; float lb = l0;
        if (l1 > lb) { best = c1; lb = l1; }
        if (l2 > lb) { best = c2; lb = l2; }
        v = best * rsqrtf(fmaxf(lb, 1e-30f));
        if (it < 1) {
            float Av0 = a00*v.x + a01*v.y + a02*v.z;
            float Av1 = a01*v.x + a11*v.y + a12*v.z;
            float Av2 = a02*v.x + a12*v.y + a22*v.z;
            lam = v.x*Av0 + v.y*Av1 + v.z*Av2;
        }
    }
    return v;
}

// planarize one finger (register-resident)
__device__ __forceinline__ void plan4(V3& p0, V3& p1, V3& p2, V3& p3){
    V3 cm = (p0 + p1 + p2 + p3) * 0.25f;
    V3 d0 = p0 - cm, d1 = p1 - cm, d2 = p2 - cm, d3 = p3 - cm;
    float a00 = d0.x*d0.x + d1.x*d1.x + d2.x*d2.x + d3.x*d3.x;
    float a01 = d0.x*d0.y + d1.x*d1.y + d2.x*d2.y + d3.x*d3.y;
    float a02 = d0.x*d0.z + d1.x*d1.z + d2.x*d2.z + d3.x*d3.z;
    float a11 = d0.y*d0.y + d1.y*d1.y + d2.y*d2.y + d3.y*d3.y;
    float a12 = d0.y*d0.z + d1.y*d1.z + d2.y*d2.z + d3.y*d3.z;
    float a22 = d0.z*d0.z + d1.z*d1.z + d2.z*d2.z + d3.z*d3.z;
    V3 n = smallest_evec(a00, a01, a02, a11, a12, a22);
    float vd = -dot3(n, cm);
    float t;
    t = dot3(p0, n) + vd; p0 = p0 - n*t;
    t = dot3(p1, n) + vd; p1 = p1 - n*t;
    t = dot3(p2, n) + vd; p2 = p2 - n*t;
    t = dot3(p3, n) + vd; p3 = p3 - n*t;
}

// abduction; palm & wristmcp precomputed (bitwise identical to in-function
// computation since their inputs are unmodified); reference EPS semantics kept.
__device__ __forceinline__ void abduct(V3 palm, V3 wristmcp,
                                       float rectC, float rectS,
                                       V3 mcp, V3& pip, V3& dip, V3& tip){
    float vd   = -dot3(mcp, palm);
    float dist = dot3(pip, palm) + vd;
    V3 projpip = pip - palm*dist;

    V3 d  = pip - mcp;
    float dis = nrm3(d);
    float invdis = __fdividef(1.0f, dis + EPSF);
    V3 mcppip = d * invdis;

    V3 e  = projpip - mcp;
    float lene = nrm3(e);
    V3 mcpproj = e * __fdividef(1.0f, lene + EPSF);
    float flex = lene * invdis;
    flex = (flex < 0.3f) ? 0.0f : flex;

    float cv = clampd(dot3(wristmcp, mcppip));
    bool overflex = cv < 0.00079632671073326f;   // == acos(cv) > 1.57

    // rect = R(palm, RECTIFY) * wristmcp  via vector Rodrigues (palm ~ unit)
    float Cr = 1.0f - rectC;
    V3 axw = cross3(palm, wristmcp);
    float adw = dot3(palm, wristmcp);
    V3 rect = wristmcp*rectC + axw*rectS + palm*(adw*Cr);

    float ang = acosf(clampd(dot3(rect, mcpproj)));
    if (overflex) ang = 0.0f;
    M3 R = getrot(ang, flex, palm, mcpproj, wristmcp);

    pip = mv(R, pip - mcp) + mcp;
    dip = mv(R, dip - mcp) + mcp;
    tip = mv(R, tip - mcp) + mcp;
}

// plane rotation; palm & wristmcp shared from caller (inputs unmodified by
// abduction -> bitwise identical to recomputation).
__device__ __forceinline__ void planerot(V3 palm, V3 wristmcp,
                                         V3 mcp, V3 pip, V3& dip, V3& tip){
    const float COS_TH120 = -0.49999997f;      // cos(3.1415926/180*120)
    const float cAP = 0.93969262078590838f;    // cos(pi/9)
    const float sAP = 0.34202014332566871f;    // sin(pi/9)

    V3 mcppip = unitv(pip - mcp);
    V3 pipdip = unitv(dip - pip);
    bool maskline = fabsf(dot3(mcppip, pipdip)) > 0.95f;
    V3 cdir = unitv(cross3(mcppip, pipdip));
    V3 stdv = unitv(cross3(wristmcp, palm));

    float x = clampd(dot3(cdir, stdv));
    float ca = (x < COS_TH120) ? -x : x;
    float sa = sqrtf(fmaxf(1.0f - x*x, 0.0f));
    if (maskline) { ca = 1.0f; sa = 0.0f; }

    float c, s;
    if (ca >= cAP) { c = 1.0f; s = 0.0f; }
    else { c = ca*cAP + sa*sAP; s = sa*cAP - ca*sAP; }
    M3 R = pick_rot(mcppip, c, s, cdir, stdv);

    dip = mv(R, dip - pip) + pip;
    tip = mv(R, tip - pip) + pip;
}

__global__ void __launch_bounds__(BLKT, 7)
handpose_kernel(const float* __restrict__ in, float* __restrict__ out, int N){
    __shared__ float s[HANDS * 63];
    int base = blockIdx.x * HANDS;
    int nE = N - base; if (nE > HANDS) nE = HANDS;
    int nF = nE * 63;
    const float* gin = in + (long long)base * 63;

    if (nE == HANDS) {
        const float4* g4 = (const float4*)gin;   // base*63*4 B divisible by 16
        float4* s4 = (float4*)s;
        for (int k = threadIdx.x; k < (HANDS*63)/4; k += BLKT)
            s4[k] = g4[k];
    } else {
        for (int k = threadIdx.x; k < nF; k += BLKT) s[k] = gin[k];
    }
    __syncthreads();

    int lane = threadIdx.x & 31;   // hand within block
    int f    = threadIdx.x >> 5;   // finger (uniform per warp)
    bool act = lane < nE;
    bool thumb = (f == 4);
    float* sp = s + lane * 63;

    float* pM = sp + 3*cMCP[f];
    float* pT = sp + 3*cTIP[f];
    float* pB = sp + 3*cPB[f];
    float rc = cRC[f], rs = cRS[f];

    V3 w, mcp, pip, dip, tip;
    if (act) {
        w   = ld3p(sp);
        mcp = ld3p(pM);
        pip = ld3p(pM + 3);
        dip = ld3p(pM + 6);
        tip = ld3p(pT);

        // ---- planarize #1 (registers) ----
        plan4(mcp, pip, dip, tip);
        st3p(pM, mcp);   // publish planarized MCP for neighbor warps
    }
    __syncthreads();

    if (act) {
        V3 pbv = ld3p(pB);    // neighbor MCP (post-plan#1; unchanged by abduction)

        // palm & wristmcp shared between abduct and planerot (inputs untouched
        // by abduction; bitwise identical to per-stage recomputation).
        V3 pa = mcp - w;
        V3 palm = unitv(cross3(pa, pbv - w));
        V3 wristmcp = unitv(pa);

        // ---- abduction ----
        abduct(palm, wristmcp, rc, rs, mcp, pip, dip, tip);
        // ---- plane rotation (fingers 0..3) ----
        if (!thumb) planerot(palm, wristmcp, mcp, pip, dip, tip);

        // planarize #2 is a provable no-op (joints remain exactly coplanar).

        st3p(pM,     mcp);
        st3p(pM + 3, pip);
        st3p(pM + 6, dip);
        st3p(pT,     tip);
    }
    __syncthreads();

    float* gout = out + (long long)base * 63;
    if (nE == HANDS) {
        const float4* s4 = (const float4*)s;
        float4* g4 = (float4*)gout;
        for (int k = threadIdx.x; k < (HANDS*63)/4; k += BLKT)
            g4[k] = s4[k];
    } else {
        for (int k = threadIdx.x; k < nF; k += BLKT) gout[k] = s[k];
    }
}

extern "C" void kernel_launch(void* const* d_in, const int* in_sizes, int n_in,
                              void* d_out, int out_size){
    const float* in = (const float*)d_in[0];
    float* out = (float*)d_out;
    int N = in_sizes[0] / 63;
    int grid = (N + HANDS - 1) / HANDS;
    handpose_kernel<<<grid, BLKT>>>(in, out, N);
}